// round 6
// baseline (speedup 1.0000x reference)
#include <cuda_runtime.h>
#include <math.h>
#include <stdint.h>

#define QLEN 1024
#define KLEN 2048
#define RLEN 2048
#define BSZ  2
#define DM   1024
#define NH   16
#define DH   64
#define NHD  1024   // NH*DH

#define BDSTRIDE 2049
#define BDSZ     2098176   // per-(b,n) shifted-BD buffer: 1023*2049+2048+1

// -------------------- scratch (device globals) ------------------------------
__device__ float g_qh[QLEN * BSZ * NHD];
__device__ float g_kv[KLEN * BSZ * 2 * NHD];
__device__ float g_rk[RLEN * NHD];
__device__ float g_bd[(size_t)BSZ * NH * BDSZ];
__device__ float g_av[QLEN * BSZ * NHD];

// -------------------- tf32 helpers ------------------------------------------
__device__ __forceinline__ uint32_t f2tf(float x) {
    uint32_t r;
    asm("cvt.rna.tf32.f32 %0, %1;" : "=r"(r) : "f"(x));
    return r;
}

__device__ __forceinline__ void mma8(float* d, const uint32_t* a, const uint32_t* b) {
    asm volatile(
        "mma.sync.aligned.m16n8k8.row.col.f32.tf32.tf32.f32 "
        "{%0,%1,%2,%3},{%4,%5,%6,%7},{%8,%9},{%0,%1,%2,%3};\n"
        : "+f"(d[0]), "+f"(d[1]), "+f"(d[2]), "+f"(d[3])
        : "r"(a[0]), "r"(a[1]), "r"(a[2]), "r"(a[3]), "r"(b[0]), "r"(b[1]));
}

// -------------------- pipelined tf32 GEMM (prefetch distance 2) -------------
// 128x128 tile, BK=16, 256 thr, 8 warps (2x4), warp tile 64x32.
// LDG for tile i+2 issued at step i; STS at end of step i+1; 2 SMEM buffers.
__global__ __launch_bounds__(256) void gemm_tf32(
    const float* __restrict__ A, const float* __restrict__ B,
    float* __restrict__ C, int M, int N, int K)
{
    __shared__ uint32_t As[2][128][20];
    __shared__ uint32_t Bs[2][16][136];
    const int tid  = threadIdx.x;
    const int lane = tid & 31;
    const int warp = tid >> 5;
    const int wm = (warp >> 2) * 64;
    const int wn = (warp & 3) * 32;
    const int row0 = blockIdx.y * 128, col0 = blockIdx.x * 128;

    float acc[4][4][4];
    #pragma unroll
    for (int i = 0; i < 4; i++)
        #pragma unroll
        for (int j = 0; j < 4; j++)
            #pragma unroll
            for (int r = 0; r < 4; r++) acc[i][j][r] = 0.0f;

    const int am = tid >> 1, aks = (tid & 1) * 8;
    const int bk = tid >> 4, bns = (tid & 15) * 8;
    const float* aptr = A + (size_t)(row0 + am) * K + aks;
    const float* bptr = B + (size_t)bk * N + col0 + bns;

    const int nsteps = K >> 4;

    // pending registers: tile to be stored at end of current step
    float4 pa0, pa1, pb0, pb1;

    // prologue: tile 0 -> buf 0; tile 1 -> pending regs
    {
        float4 a0 = *(const float4*)(aptr);
        float4 a1 = *(const float4*)(aptr + 4);
        float4 b0 = *(const float4*)(bptr);
        float4 b1 = *(const float4*)(bptr + 4);
        *(uint4*)&As[0][am][aks]     = make_uint4(f2tf(a0.x), f2tf(a0.y), f2tf(a0.z), f2tf(a0.w));
        *(uint4*)&As[0][am][aks + 4] = make_uint4(f2tf(a1.x), f2tf(a1.y), f2tf(a1.z), f2tf(a1.w));
        *(uint4*)&Bs[0][bk][bns]     = make_uint4(f2tf(b0.x), f2tf(b0.y), f2tf(b0.z), f2tf(b0.w));
        *(uint4*)&Bs[0][bk][bns + 4] = make_uint4(f2tf(b1.x), f2tf(b1.y), f2tf(b1.z), f2tf(b1.w));
        pa0 = *(const float4*)(aptr + 16);
        pa1 = *(const float4*)(aptr + 20);
        pb0 = *(const float4*)(bptr + (size_t)16 * N);
        pb1 = *(const float4*)(bptr + (size_t)16 * N + 4);
    }
    __syncthreads();

    for (int i = 0; i < nsteps; i++) {
        const int buf = i & 1;

        // issue LDG for tile i+2 (lands during steps i and i+1)
        float4 na0, na1, nb0, nb1;
        const bool ld2 = (i + 2) < nsteps;
        if (ld2) {
            int k2 = (i + 2) << 4;
            na0 = *(const float4*)(aptr + k2);
            na1 = *(const float4*)(aptr + k2 + 4);
            nb0 = *(const float4*)(bptr + (size_t)k2 * N);
            nb1 = *(const float4*)(bptr + (size_t)k2 * N + 4);
        }

        #pragma unroll
        for (int kk = 0; kk < 16; kk += 8) {
            uint32_t af[4][4];
            #pragma unroll
            for (int mt = 0; mt < 4; mt++) {
                int r = wm + mt * 16 + (lane >> 2);
                int c = kk + (lane & 3);
                af[mt][0] = As[buf][r][c];
                af[mt][1] = As[buf][r + 8][c];
                af[mt][2] = As[buf][r][c + 4];
                af[mt][3] = As[buf][r + 8][c + 4];
            }
            #pragma unroll
            for (int nt = 0; nt < 4; nt++) {
                uint32_t bf[2];
                int n = wn + nt * 8 + (lane >> 2);
                bf[0] = Bs[buf][kk + (lane & 3)][n];
                bf[1] = Bs[buf][kk + 4 + (lane & 3)][n];
                #pragma unroll
                for (int mt = 0; mt < 4; mt++) mma8(acc[mt][nt], af[mt], bf);
            }
        }

        // store pending tile (i+1) into the other buffer
        if ((i + 1) < nsteps) {
            int nb = buf ^ 1;
            *(uint4*)&As[nb][am][aks]     = make_uint4(f2tf(pa0.x), f2tf(pa0.y), f2tf(pa0.z), f2tf(pa0.w));
            *(uint4*)&As[nb][am][aks + 4] = make_uint4(f2tf(pa1.x), f2tf(pa1.y), f2tf(pa1.z), f2tf(pa1.w));
            *(uint4*)&Bs[nb][bk][bns]     = make_uint4(f2tf(pb0.x), f2tf(pb0.y), f2tf(pb0.z), f2tf(pb0.w));
            *(uint4*)&Bs[nb][bk][bns + 4] = make_uint4(f2tf(pb1.x), f2tf(pb1.y), f2tf(pb1.z), f2tf(pb1.w));
        }
        if (ld2) { pa0 = na0; pa1 = na1; pb0 = nb0; pb1 = nb1; }
        __syncthreads();
    }

    #pragma unroll
    for (int mt = 0; mt < 4; mt++)
        #pragma unroll
        for (int nt = 0; nt < 4; nt++) {
            int r = row0 + wm + mt * 16 + (lane >> 2);
            int c = col0 + wn + nt * 8 + 2 * (lane & 3);
            *(float2*)&C[(size_t)r * N + c]       = make_float2(acc[mt][nt][0], acc[mt][nt][1]);
            *(float2*)&C[(size_t)(r + 8) * N + c] = make_float2(acc[mt][nt][2], acc[mt][nt][3]);
        }
}

// -------------------- BD scores (tf32) -> shifted layout --------------------
extern __shared__ uint32_t s_dyn[];
__global__ __launch_bounds__(256) void scores_bd_tf32(
    const float* __restrict__ qh, const float* __restrict__ rk,
    const float* __restrict__ bias, float* __restrict__ out)
{
    uint32_t (*Qs)[68] = (uint32_t(*)[68])s_dyn;
    uint32_t (*Ks)[68] = (uint32_t(*)[68])(s_dyn + 128 * 68);

    const int bn = blockIdx.z;
    const int b = bn >> 4, n = bn & 15;
    const int j0 = blockIdx.x * 128, i0 = blockIdx.y * 128;
    const int tid  = threadIdx.x;
    const int lane = tid & 31;
    const int warp = tid >> 5;
    const int wm = (warp >> 2) * 64;
    const int wn = (warp & 3) * 32;

    const int m = tid >> 1, half = (tid & 1) * 32;
    const float* qrow = qh + (size_t)((i0 + m) * 2 + b) * NHD + n * DH + half;
    const float* krow = rk + (size_t)(j0 + m) * NHD + n * DH + half;
    const float4* bias4 = (const float4*)(bias + n * DH + half);

    #pragma unroll
    for (int q = 0; q < 8; q++) {
        float4 qv = ((const float4*)qrow)[q];
        float4 bv = bias4[q];
        int d = half + q * 4;
        *(uint4*)&Qs[m][d] = make_uint4(f2tf(qv.x + bv.x), f2tf(qv.y + bv.y),
                                        f2tf(qv.z + bv.z), f2tf(qv.w + bv.w));
        float4 kv4 = ((const float4*)krow)[q];
        *(uint4*)&Ks[m][d] = make_uint4(f2tf(kv4.x), f2tf(kv4.y), f2tf(kv4.z), f2tf(kv4.w));
    }
    __syncthreads();

    float acc[4][4][4];
    #pragma unroll
    for (int i = 0; i < 4; i++)
        #pragma unroll
        for (int j = 0; j < 4; j++)
            #pragma unroll
            for (int r = 0; r < 4; r++) acc[i][j][r] = 0.0f;

    #pragma unroll
    for (int kk = 0; kk < 64; kk += 8) {
        uint32_t af[4][4];
        #pragma unroll
        for (int mt = 0; mt < 4; mt++) {
            int r = wm + mt * 16 + (lane >> 2);
            int c = kk + (lane & 3);
            af[mt][0] = Qs[r][c];
            af[mt][1] = Qs[r + 8][c];
            af[mt][2] = Qs[r][c + 4];
            af[mt][3] = Qs[r + 8][c + 4];
        }
        #pragma unroll
        for (int nt = 0; nt < 4; nt++) {
            uint32_t bf[2];
            int j = wn + nt * 8 + (lane >> 2);
            bf[0] = Ks[j][kk + (lane & 3)];
            bf[1] = Ks[j][kk + 4 + (lane & 3)];
            #pragma unroll
            for (int mt = 0; mt < 4; mt++) mma8(acc[mt][nt], af[mt], bf);
        }
    }

    float* ob = out + (size_t)bn * BDSZ;
    #pragma unroll
    for (int mt = 0; mt < 4; mt++)
        #pragma unroll
        for (int nt = 0; nt < 4; nt++) {
            int r = i0 + wm + mt * 16 + (lane >> 2);
            int c = j0 + wn + nt * 8 + 2 * (lane & 3);
            size_t p0 = (size_t)r * BDSTRIDE + c + 1;
            size_t p1 = (size_t)(r + 8) * BDSTRIDE + c + 1;
            ob[p0]     = acc[mt][nt][0];
            ob[p0 + 1] = acc[mt][nt][1];
            ob[p1]     = acc[mt][nt][2];
            ob[p1 + 1] = acc[mt][nt][3];
        }
}

// zero the "dropped column" positions of the shifted buffer
__global__ void zero_diag(float* __restrict__ buf) {
    int k = blockIdx.x * blockDim.x + threadIdx.x;
    int bn = k >> 10, kk = k & 1023;
    if (kk >= 1)
        buf[(size_t)bn * BDSZ + (size_t)kk * BDSTRIDE] = 0.0f;
}

// -------------------- fused attention v2 ------------------------------------
__global__ __launch_bounds__(128, 2) void attn_fused(
    const float* __restrict__ qh, const float* __restrict__ kv,
    const float* __restrict__ bdbuf, const float* __restrict__ rwb,
    float* __restrict__ av)
{
    extern __shared__ uint32_t smem[];
    uint32_t (*Ks)[68] = (uint32_t(*)[68])smem;
    uint32_t (*Vs)[72] = (uint32_t(*)[72])(smem + 128 * 68);

    const int bn = blockIdx.y;
    const int b = bn >> 4, n = bn & 15;
    const int i0 = blockIdx.x * 128;
    const int tid  = threadIdx.x;
    const int lane = tid & 31;
    const int warp = tid >> 5;
    const int row = lane >> 2;
    const int qd  = lane & 3;
    int irow[2];
    irow[0] = i0 + warp * 32 + row;
    irow[1] = irow[0] + 16;

    uint32_t qf[2][8][4];
    #pragma unroll
    for (int mt = 0; mt < 2; mt++) {
        const float* q0 = qh + (size_t)(irow[mt] * 2 + b) * NHD + n * DH;
        const float* q1 = q0 + 16 * NHD;
        const float* bias = rwb + n * DH;
        #pragma unroll
        for (int g = 0; g < 8; g++) {
            int d0 = g * 8 + qd, d1 = d0 + 4;
            qf[mt][g][0] = f2tf(q0[d0] + bias[d0]);
            qf[mt][g][1] = f2tf(q1[d0] + bias[d0]);
            qf[mt][g][2] = f2tf(q0[d1] + bias[d1]);
            qf[mt][g][3] = f2tf(q1[d1] + bias[d1]);
        }
    }

    float Ov[2][8][4];
    #pragma unroll
    for (int mt = 0; mt < 2; mt++)
        #pragma unroll
        for (int dt = 0; dt < 8; dt++)
            #pragma unroll
            for (int r = 0; r < 4; r++) Ov[mt][dt][r] = 0.0f;
    float mrow[2][2] = {{-3.402823466e38f, -3.402823466e38f},
                        {-3.402823466e38f, -3.402823466e38f}};
    float lrow[2][2] = {{0.0f, 0.0f}, {0.0f, 0.0f}};

    const float* bdp = bdbuf + (size_t)bn * BDSZ + 1024;

    const int srcA = (lane & 28) | (qd >> 1);
    const int srcB = srcA | 2;
    const bool odd = qd & 1;

    for (int j0 = 0; j0 < KLEN; j0 += 128) {
        __syncthreads();
        #pragma unroll
        for (int it = 0; it < 16; it++) {
            int fi = tid + it * 128;
            int r = fi >> 4, c4 = (fi & 15) * 4;
            const float* base = kv + ((size_t)(j0 + r) * 2 + b) * (2 * NHD) + n * DH + c4;
            float4 kx = *(const float4*)base;
            *(uint4*)&Ks[r][c4] = make_uint4(f2tf(kx.x), f2tf(kx.y), f2tf(kx.z), f2tf(kx.w));
            float4 vx = *(const float4*)(base + NHD);
            *(uint4*)&Vs[r][c4] = make_uint4(f2tf(vx.x), f2tf(vx.y), f2tf(vx.z), f2tf(vx.w));
        }
        __syncthreads();

        #pragma unroll
        for (int ch = 0; ch < 2; ch++) {
            const int jl = ch * 64;

            float s[2][8][4];
            #pragma unroll
            for (int mt = 0; mt < 2; mt++)
                #pragma unroll
                for (int nt = 0; nt < 8; nt++)
                    #pragma unroll
                    for (int r = 0; r < 4; r++) s[mt][nt][r] = 0.0f;

            #pragma unroll
            for (int g = 0; g < 8; g++) {
                #pragma unroll
                for (int nt = 0; nt < 8; nt++) {
                    uint32_t bf[2];
                    int j = jl + nt * 8 + row;
                    bf[0] = Ks[j][g * 8 + qd];
                    bf[1] = Ks[j][g * 8 + 4 + qd];
                    mma8(s[0][nt], qf[0][g], bf);
                    mma8(s[1][nt], qf[1][g], bf);
                }
            }

            #pragma unroll
            for (int mt = 0; mt < 2; mt++) {
                #pragma unroll
                for (int nt = 0; nt < 8; nt++) {
                    int jc = j0 + jl + nt * 8 + 2 * qd;
                    float2 b0 = *(const float2*)(bdp + (size_t)irow[mt] * KLEN + jc);
                    float2 b1 = *(const float2*)(bdp + (size_t)(irow[mt] + 8) * KLEN + jc);
                    s[mt][nt][0] = (s[mt][nt][0] + b0.x) * 0.125f;
                    s[mt][nt][1] = (s[mt][nt][1] + b0.y) * 0.125f;
                    s[mt][nt][2] = (s[mt][nt][2] + b1.x) * 0.125f;
                    s[mt][nt][3] = (s[mt][nt][3] + b1.y) * 0.125f;
                }
            }

            #pragma unroll
            for (int mt = 0; mt < 2; mt++) {
                float tm0 = -3.402823466e38f, tm1 = -3.402823466e38f;
                #pragma unroll
                for (int nt = 0; nt < 8; nt++) {
                    tm0 = fmaxf(tm0, fmaxf(s[mt][nt][0], s[mt][nt][1]));
                    tm1 = fmaxf(tm1, fmaxf(s[mt][nt][2], s[mt][nt][3]));
                }
                tm0 = fmaxf(tm0, __shfl_xor_sync(0xffffffffu, tm0, 1));
                tm0 = fmaxf(tm0, __shfl_xor_sync(0xffffffffu, tm0, 2));
                tm1 = fmaxf(tm1, __shfl_xor_sync(0xffffffffu, tm1, 1));
                tm1 = fmaxf(tm1, __shfl_xor_sync(0xffffffffu, tm1, 2));

                float nm0 = fmaxf(mrow[mt][0], tm0), nm1 = fmaxf(mrow[mt][1], tm1);
                float sc0 = __expf(mrow[mt][0] - nm0), sc1 = __expf(mrow[mt][1] - nm1);
                mrow[mt][0] = nm0; mrow[mt][1] = nm1;

                float ps0 = 0.0f, ps1 = 0.0f;
                #pragma unroll
                for (int nt = 0; nt < 8; nt++) {
                    s[mt][nt][0] = __expf(s[mt][nt][0] - nm0);
                    s[mt][nt][1] = __expf(s[mt][nt][1] - nm0);
                    s[mt][nt][2] = __expf(s[mt][nt][2] - nm1);
                    s[mt][nt][3] = __expf(s[mt][nt][3] - nm1);
                    ps0 += s[mt][nt][0] + s[mt][nt][1];
                    ps1 += s[mt][nt][2] + s[mt][nt][3];
                }
                lrow[mt][0] = lrow[mt][0] * sc0 + ps0;
                lrow[mt][1] = lrow[mt][1] * sc1 + ps1;
                #pragma unroll
                for (int dt = 0; dt < 8; dt++) {
                    Ov[mt][dt][0] *= sc0; Ov[mt][dt][1] *= sc0;
                    Ov[mt][dt][2] *= sc1; Ov[mt][dt][3] *= sc1;
                }
            }

            #pragma unroll
            for (int g = 0; g < 8; g++) {
                uint32_t a[2][4];
                #pragma unroll
                for (int mt = 0; mt < 2; mt++) {
                    uint32_t p0 = f2tf(s[mt][g][0]), p1 = f2tf(s[mt][g][1]);
                    uint32_t p2 = f2tf(s[mt][g][2]), p3 = f2tf(s[mt][g][3]);
                    uint32_t t00 = __shfl_sync(0xffffffffu, p0, srcA);
                    uint32_t t01 = __shfl_sync(0xffffffffu, p1, srcA);
                    uint32_t t10 = __shfl_sync(0xffffffffu, p2, srcA);
                    uint32_t t11 = __shfl_sync(0xffffffffu, p3, srcA);
                    uint32_t u00 = __shfl_sync(0xffffffffu, p0, srcB);
                    uint32_t u01 = __shfl_sync(0xffffffffu, p1, srcB);
                    uint32_t u10 = __shfl_sync(0xffffffffu, p2, srcB);
                    uint32_t u11 = __shfl_sync(0xffffffffu, p3, srcB);
                    a[mt][0] = odd ? t01 : t00;
                    a[mt][1] = odd ? t11 : t10;
                    a[mt][2] = odd ? u01 : u00;
                    a[mt][3] = odd ? u11 : u10;
                }
                #pragma unroll
                for (int dt = 0; dt < 8; dt++) {
                    uint32_t bf[2];
                    bf[0] = Vs[jl + g * 8 + qd][dt * 8 + row];
                    bf[1] = Vs[jl + g * 8 + 4 + qd][dt * 8 + row];
                    mma8(Ov[0][dt], a[0], bf);
                    mma8(Ov[1][dt], a[1], bf);
                }
            }
        }
    }

    #pragma unroll
    for (int mt = 0; mt < 2; mt++) {
        float l0 = lrow[mt][0], l1 = lrow[mt][1];
        l0 += __shfl_xor_sync(0xffffffffu, l0, 1);
        l0 += __shfl_xor_sync(0xffffffffu, l0, 2);
        l1 += __shfl_xor_sync(0xffffffffu, l1, 1);
        l1 += __shfl_xor_sync(0xffffffffu, l1, 2);
        float inv0 = 1.0f / l0, inv1 = 1.0f / l1;
        #pragma unroll
        for (int dt = 0; dt < 8; dt++) {
            int d = n * DH + dt * 8 + 2 * qd;
            *(float2*)&av[(size_t)(irow[mt] * 2 + b) * NHD + d] =
                make_float2(Ov[mt][dt][0] * inv0, Ov[mt][dt][1] * inv0);
            *(float2*)&av[(size_t)((irow[mt] + 8) * 2 + b) * NHD + d] =
                make_float2(Ov[mt][dt][2] * inv1, Ov[mt][dt][3] * inv1);
        }
    }
}

// ---------------------------------------------------------------------------
extern "C" void kernel_launch(void* const* d_in, const int* in_sizes, int n_in,
                              void* d_out, int out_size)
{
    const float* w   = (const float*)d_in[0];
    const float* r   = (const float*)d_in[1];
    const float* rwb = (const float*)d_in[2];
    const float* rrb = (const float*)d_in[3];
    const float* Wq  = (const float*)d_in[4];
    const float* Wkv = (const float*)d_in[5];
    const float* Wr  = (const float*)d_in[6];
    const float* Wo  = (const float*)d_in[7];
    float* out = (float*)d_out;

    float *qh, *kv, *rk, *bd, *av;
    cudaGetSymbolAddress((void**)&qh, g_qh);
    cudaGetSymbolAddress((void**)&kv, g_kv);
    cudaGetSymbolAddress((void**)&rk, g_rk);
    cudaGetSymbolAddress((void**)&bd, g_bd);
    cudaGetSymbolAddress((void**)&av, g_av);

    static cudaStream_t st1 = 0, st2 = 0;
    static cudaEvent_t ev0 = 0, evKV = 0, evR = 0;
    if (!st1) {
        cudaStreamCreateWithFlags(&st1, cudaStreamNonBlocking);
        cudaStreamCreateWithFlags(&st2, cudaStreamNonBlocking);
        cudaEventCreateWithFlags(&ev0,  cudaEventDisableTiming);
        cudaEventCreateWithFlags(&evKV, cudaEventDisableTiming);
        cudaEventCreateWithFlags(&evR,  cudaEventDisableTiming);
        cudaFuncSetAttribute(scores_bd_tf32,
                             cudaFuncAttributeMaxDynamicSharedMemorySize,
                             2 * 128 * 68 * 4);
        cudaFuncSetAttribute(attn_fused,
                             cudaFuncAttributeMaxDynamicSharedMemorySize,
                             (128 * 68 + 128 * 72) * 4);
    }
    const int score_smem = 2 * 128 * 68 * 4;
    const int fused_smem = (128 * 68 + 128 * 72) * 4;

    cudaEventRecord(ev0, 0);
    cudaStreamWaitEvent(st1, ev0, 0);
    cudaStreamWaitEvent(st2, ev0, 0);

    // stream 0: Wq projection
    gemm_tf32<<<dim3(1024 / 128, 2048 / 128), 256, 0, 0>>>(
        w + (size_t)QLEN * BSZ * DM, Wq, qh, 2048, 1024, 1024);

    // st1: Wkv projection (largest, overlapped)
    gemm_tf32<<<dim3(2048 / 128, 4096 / 128), 256, 0, st1>>>(
        w, Wkv, kv, 4096, 2048, 1024);
    cudaEventRecord(evKV, st1);

    // st2: zero diag + Wr projection
    zero_diag<<<32, 1024, 0, st2>>>(bd);
    gemm_tf32<<<dim3(1024 / 128, 2048 / 128), 256, 0, st2>>>(
        r, Wr, rk, 2048, 1024, 1024);
    cudaEventRecord(evR, st2);

    // stream 0: BD scores
    cudaStreamWaitEvent(0, evR, 0);
    scores_bd_tf32<<<dim3(RLEN / 128, QLEN / 128, 32), 256, score_smem, 0>>>(
        qh, rk, rrb, bd);

    // stream 0: fused attention
    cudaStreamWaitEvent(0, evKV, 0);
    attn_fused<<<dim3(QLEN / 128, BSZ * NH), 128, fused_smem, 0>>>(
        qh, kv, bd, rwb, av);

    // output projection
    gemm_tf32<<<dim3(1024 / 128, 2048 / 128), 256, 0, 0>>>(
        av, Wo, out, 2048, 1024, 1024);
}

// round 7
// speedup vs baseline: 1.0759x; 1.0759x over previous
#include <cuda_runtime.h>
#include <math.h>
#include <stdint.h>

#define QLEN 1024
#define KLEN 2048
#define RLEN 2048
#define BSZ  2
#define DM   1024
#define NH   16
#define DH   64
#define NHD  1024   // NH*DH

#define BDSTRIDE 2049
#define BDSZ     2098176   // per-(b,n) shifted-BD buffer: 1023*2049+2048+1

// -------------------- scratch (device globals) ------------------------------
__device__ float g_qh[QLEN * BSZ * NHD];
__device__ float g_kv[KLEN * BSZ * 2 * NHD];
__device__ float g_rk[RLEN * NHD];
__device__ float g_bd[(size_t)BSZ * NH * BDSZ];
__device__ float g_av[QLEN * BSZ * NHD];

// -------------------- helpers ------------------------------------------------
__device__ __forceinline__ uint32_t f2tf(float x) {
    uint32_t r;
    asm("cvt.rna.tf32.f32 %0, %1;" : "=r"(r) : "f"(x));
    return r;
}

__device__ __forceinline__ void mma8(float* d, const uint32_t* a, const uint32_t* b) {
    asm volatile(
        "mma.sync.aligned.m16n8k8.row.col.f32.tf32.tf32.f32 "
        "{%0,%1,%2,%3},{%4,%5,%6,%7},{%8,%9},{%0,%1,%2,%3};\n"
        : "+f"(d[0]), "+f"(d[1]), "+f"(d[2]), "+f"(d[3])
        : "r"(a[0]), "r"(a[1]), "r"(a[2]), "r"(a[3]), "r"(b[0]), "r"(b[1]));
}

__device__ __forceinline__ void cpa16(uint32_t dst, const void* src) {
    asm volatile("cp.async.ca.shared.global [%0], [%1], 16;" :: "r"(dst), "l"(src));
}
__device__ __forceinline__ void cpa_commit() {
    asm volatile("cp.async.commit_group;");
}
template<int N> __device__ __forceinline__ void cpa_wait() {
    asm volatile("cp.async.wait_group %0;" :: "n"(N));
}

// -------------------- pipelined tf32 GEMM (prefetch distance 2) -------------
__global__ __launch_bounds__(256) void gemm_tf32(
    const float* __restrict__ A, const float* __restrict__ B,
    float* __restrict__ C, int M, int N, int K)
{
    __shared__ uint32_t As[2][128][20];
    __shared__ uint32_t Bs[2][16][136];
    const int tid  = threadIdx.x;
    const int lane = tid & 31;
    const int warp = tid >> 5;
    const int wm = (warp >> 2) * 64;
    const int wn = (warp & 3) * 32;
    const int row0 = blockIdx.y * 128, col0 = blockIdx.x * 128;

    float acc[4][4][4];
    #pragma unroll
    for (int i = 0; i < 4; i++)
        #pragma unroll
        for (int j = 0; j < 4; j++)
            #pragma unroll
            for (int r = 0; r < 4; r++) acc[i][j][r] = 0.0f;

    const int am = tid >> 1, aks = (tid & 1) * 8;
    const int bk = tid >> 4, bns = (tid & 15) * 8;
    const float* aptr = A + (size_t)(row0 + am) * K + aks;
    const float* bptr = B + (size_t)bk * N + col0 + bns;

    const int nsteps = K >> 4;
    float4 pa0, pa1, pb0, pb1;

    {
        float4 a0 = *(const float4*)(aptr);
        float4 a1 = *(const float4*)(aptr + 4);
        float4 b0 = *(const float4*)(bptr);
        float4 b1 = *(const float4*)(bptr + 4);
        *(uint4*)&As[0][am][aks]     = make_uint4(f2tf(a0.x), f2tf(a0.y), f2tf(a0.z), f2tf(a0.w));
        *(uint4*)&As[0][am][aks + 4] = make_uint4(f2tf(a1.x), f2tf(a1.y), f2tf(a1.z), f2tf(a1.w));
        *(uint4*)&Bs[0][bk][bns]     = make_uint4(f2tf(b0.x), f2tf(b0.y), f2tf(b0.z), f2tf(b0.w));
        *(uint4*)&Bs[0][bk][bns + 4] = make_uint4(f2tf(b1.x), f2tf(b1.y), f2tf(b1.z), f2tf(b1.w));
        pa0 = *(const float4*)(aptr + 16);
        pa1 = *(const float4*)(aptr + 20);
        pb0 = *(const float4*)(bptr + (size_t)16 * N);
        pb1 = *(const float4*)(bptr + (size_t)16 * N + 4);
    }
    __syncthreads();

    for (int i = 0; i < nsteps; i++) {
        const int buf = i & 1;
        float4 na0, na1, nb0, nb1;
        const bool ld2 = (i + 2) < nsteps;
        if (ld2) {
            int k2 = (i + 2) << 4;
            na0 = *(const float4*)(aptr + k2);
            na1 = *(const float4*)(aptr + k2 + 4);
            nb0 = *(const float4*)(bptr + (size_t)k2 * N);
            nb1 = *(const float4*)(bptr + (size_t)k2 * N + 4);
        }

        #pragma unroll
        for (int kk = 0; kk < 16; kk += 8) {
            uint32_t af[4][4];
            #pragma unroll
            for (int mt = 0; mt < 4; mt++) {
                int r = wm + mt * 16 + (lane >> 2);
                int c = kk + (lane & 3);
                af[mt][0] = As[buf][r][c];
                af[mt][1] = As[buf][r + 8][c];
                af[mt][2] = As[buf][r][c + 4];
                af[mt][3] = As[buf][r + 8][c + 4];
            }
            #pragma unroll
            for (int nt = 0; nt < 4; nt++) {
                uint32_t bf[2];
                int n = wn + nt * 8 + (lane >> 2);
                bf[0] = Bs[buf][kk + (lane & 3)][n];
                bf[1] = Bs[buf][kk + 4 + (lane & 3)][n];
                #pragma unroll
                for (int mt = 0; mt < 4; mt++) mma8(acc[mt][nt], af[mt], bf);
            }
        }

        if ((i + 1) < nsteps) {
            int nb = buf ^ 1;
            *(uint4*)&As[nb][am][aks]     = make_uint4(f2tf(pa0.x), f2tf(pa0.y), f2tf(pa0.z), f2tf(pa0.w));
            *(uint4*)&As[nb][am][aks + 4] = make_uint4(f2tf(pa1.x), f2tf(pa1.y), f2tf(pa1.z), f2tf(pa1.w));
            *(uint4*)&Bs[nb][bk][bns]     = make_uint4(f2tf(pb0.x), f2tf(pb0.y), f2tf(pb0.z), f2tf(pb0.w));
            *(uint4*)&Bs[nb][bk][bns + 4] = make_uint4(f2tf(pb1.x), f2tf(pb1.y), f2tf(pb1.z), f2tf(pb1.w));
        }
        if (ld2) { pa0 = na0; pa1 = na1; pb0 = nb0; pb1 = nb1; }
        __syncthreads();
    }

    #pragma unroll
    for (int mt = 0; mt < 4; mt++)
        #pragma unroll
        for (int nt = 0; nt < 4; nt++) {
            int r = row0 + wm + mt * 16 + (lane >> 2);
            int c = col0 + wn + nt * 8 + 2 * (lane & 3);
            *(float2*)&C[(size_t)r * N + c]       = make_float2(acc[mt][nt][0], acc[mt][nt][1]);
            *(float2*)&C[(size_t)(r + 8) * N + c] = make_float2(acc[mt][nt][2], acc[mt][nt][3]);
        }
}

// -------------------- BD scores (tf32) -> shifted layout --------------------
extern __shared__ uint32_t s_dyn[];
__global__ __launch_bounds__(256) void scores_bd_tf32(
    const float* __restrict__ qh, const float* __restrict__ rk,
    const float* __restrict__ bias, float* __restrict__ out)
{
    uint32_t (*Qs)[68] = (uint32_t(*)[68])s_dyn;
    uint32_t (*Ks)[68] = (uint32_t(*)[68])(s_dyn + 128 * 68);

    const int bn = blockIdx.z;
    const int b = bn >> 4, n = bn & 15;
    const int j0 = blockIdx.x * 128, i0 = blockIdx.y * 128;
    const int tid  = threadIdx.x;
    const int lane = tid & 31;
    const int warp = tid >> 5;
    const int wm = (warp >> 2) * 64;
    const int wn = (warp & 3) * 32;

    const int m = tid >> 1, half = (tid & 1) * 32;
    const float* qrow = qh + (size_t)((i0 + m) * 2 + b) * NHD + n * DH + half;
    const float* krow = rk + (size_t)(j0 + m) * NHD + n * DH + half;
    const float4* bias4 = (const float4*)(bias + n * DH + half);

    #pragma unroll
    for (int q = 0; q < 8; q++) {
        float4 qv = ((const float4*)qrow)[q];
        float4 bv = bias4[q];
        int d = half + q * 4;
        *(uint4*)&Qs[m][d] = make_uint4(f2tf(qv.x + bv.x), f2tf(qv.y + bv.y),
                                        f2tf(qv.z + bv.z), f2tf(qv.w + bv.w));
        float4 kv4 = ((const float4*)krow)[q];
        *(uint4*)&Ks[m][d] = make_uint4(f2tf(kv4.x), f2tf(kv4.y), f2tf(kv4.z), f2tf(kv4.w));
    }
    __syncthreads();

    float acc[4][4][4];
    #pragma unroll
    for (int i = 0; i < 4; i++)
        #pragma unroll
        for (int j = 0; j < 4; j++)
            #pragma unroll
            for (int r = 0; r < 4; r++) acc[i][j][r] = 0.0f;

    #pragma unroll
    for (int kk = 0; kk < 64; kk += 8) {
        uint32_t af[4][4];
        #pragma unroll
        for (int mt = 0; mt < 4; mt++) {
            int r = wm + mt * 16 + (lane >> 2);
            int c = kk + (lane & 3);
            af[mt][0] = Qs[r][c];
            af[mt][1] = Qs[r + 8][c];
            af[mt][2] = Qs[r][c + 4];
            af[mt][3] = Qs[r + 8][c + 4];
        }
        #pragma unroll
        for (int nt = 0; nt < 4; nt++) {
            uint32_t bf[2];
            int j = wn + nt * 8 + (lane >> 2);
            bf[0] = Ks[j][kk + (lane & 3)];
            bf[1] = Ks[j][kk + 4 + (lane & 3)];
            #pragma unroll
            for (int mt = 0; mt < 4; mt++) mma8(acc[mt][nt], af[mt], bf);
        }
    }

    float* ob = out + (size_t)bn * BDSZ;
    #pragma unroll
    for (int mt = 0; mt < 4; mt++)
        #pragma unroll
        for (int nt = 0; nt < 4; nt++) {
            int r = i0 + wm + mt * 16 + (lane >> 2);
            int c = j0 + wn + nt * 8 + 2 * (lane & 3);
            size_t p0 = (size_t)r * BDSTRIDE + c + 1;
            size_t p1 = (size_t)(r + 8) * BDSTRIDE + c + 1;
            ob[p0]     = acc[mt][nt][0];
            ob[p0 + 1] = acc[mt][nt][1];
            ob[p1]     = acc[mt][nt][2];
            ob[p1 + 1] = acc[mt][nt][3];
        }
}

// zero the "dropped column" positions of the shifted buffer
__global__ void zero_diag(float* __restrict__ buf) {
    int k = blockIdx.x * blockDim.x + threadIdx.x;
    int bn = k >> 10, kk = k & 1023;
    if (kk >= 1)
        buf[(size_t)bn * BDSZ + (size_t)kk * BDSTRIDE] = 0.0f;
}

// -------------------- fused attention v3: cp.async pipelined -----------------
// grid (QLEN/128, 32), 128 threads = 4 warps, warp = 32 q-rows (mt=2).
// K double-buffered, V single-buffered; K/V staged raw fp32 (tf32 truncation).
// s-accumulators initialized with shifted-BD values (hides BD LDG latency).
#define KWORDS (128 * 68)
#define VBASE  (2 * KWORDS)
__global__ __launch_bounds__(128, 2) void attn_fused(
    const float* __restrict__ qh, const float* __restrict__ kv,
    const float* __restrict__ bdbuf, const float* __restrict__ rwb,
    float* __restrict__ av)
{
    extern __shared__ uint32_t smem[];
    uint32_t (*KsA)[68] = (uint32_t(*)[68])smem;            // 2 bufs: rows [buf*128 + r]
    uint32_t (*Vs)[72]  = (uint32_t(*)[72])(smem + VBASE);
    const uint32_t sbase = (uint32_t)__cvta_generic_to_shared(smem);

    const int bn = blockIdx.y;
    const int b = bn >> 4, n = bn & 15;
    const int i0 = blockIdx.x * 128;
    const int tid  = threadIdx.x;
    const int lane = tid & 31;
    const int warp = tid >> 5;
    const int row = lane >> 2;
    const int qd  = lane & 3;
    int irow[2];
    irow[0] = i0 + warp * 32 + row;
    irow[1] = irow[0] + 16;

    // staging thread mapping: 16 iters x (row = fi>>4, 16B chunk = fi&15)
    const int st_row = tid >> 4;           // base row, +8 per iter... (fi>>4 = tid>>4 + it*8)
    const int st_c4  = (tid & 15) * 4;     // float offset within row

    // ---- Q fragments with r_w_bias folded in ----
    uint32_t qf[2][8][4];
    #pragma unroll
    for (int mt = 0; mt < 2; mt++) {
        const float* q0 = qh + (size_t)(irow[mt] * 2 + b) * NHD + n * DH;
        const float* q1 = q0 + 16 * NHD;
        const float* bias = rwb + n * DH;
        #pragma unroll
        for (int g = 0; g < 8; g++) {
            int d0 = g * 8 + qd, d1 = d0 + 4;
            qf[mt][g][0] = f2tf(q0[d0] + bias[d0]);
            qf[mt][g][1] = f2tf(q1[d0] + bias[d0]);
            qf[mt][g][2] = f2tf(q0[d1] + bias[d1]);
            qf[mt][g][3] = f2tf(q1[d1] + bias[d1]);
        }
    }

    float Ov[2][8][4];
    #pragma unroll
    for (int mt = 0; mt < 2; mt++)
        #pragma unroll
        for (int dt = 0; dt < 8; dt++)
            #pragma unroll
            for (int r = 0; r < 4; r++) Ov[mt][dt][r] = 0.0f;
    float mrow[2][2] = {{-3.402823466e38f, -3.402823466e38f},
                        {-3.402823466e38f, -3.402823466e38f}};
    float lrow[2][2] = {{0.0f, 0.0f}, {0.0f, 0.0f}};

    const float* bdp = bdbuf + (size_t)bn * BDSZ + 1024;

    const int srcA = (lane & 28) | (qd >> 1);
    const int srcB = srcA | 2;
    const bool odd = qd & 1;

    // ---- prologue: stage K[0] (group), V[0] (group) ----
    #pragma unroll
    for (int it = 0; it < 16; it++) {
        int r = st_row + it * 8;
        const float* src = kv + ((size_t)r * 2 + b) * (2 * NHD) + n * DH + st_c4;
        cpa16(sbase + (uint32_t)(r * 68 + st_c4) * 4, src);
    }
    cpa_commit();
    #pragma unroll
    for (int it = 0; it < 16; it++) {
        int r = st_row + it * 8;
        const float* src = kv + ((size_t)r * 2 + b) * (2 * NHD) + NHD + n * DH + st_c4;
        cpa16(sbase + (uint32_t)(VBASE + r * 72 + st_c4) * 4, src);
    }
    cpa_commit();

    for (int t = 0; t < 16; t++) {
        const int j0 = t * 128;
        const int kb = t & 1;

        // K[t] ready (pending after wait: V[t])
        cpa_wait<1>();
        __syncthreads();

        // issue K[t+1] into other buffer (hidden under softmax+PV)
        if (t + 1 < 16) {
            const int kboff = (kb ^ 1) * KWORDS;
            #pragma unroll
            for (int it = 0; it < 16; it++) {
                int r = st_row + it * 8;
                const float* src = kv + ((size_t)(j0 + 128 + r) * 2 + b) * (2 * NHD) + n * DH + st_c4;
                cpa16(sbase + (uint32_t)(kboff + r * 68 + st_c4) * 4, src);
            }
        }
        cpa_commit();

        #pragma unroll
        for (int ch = 0; ch < 2; ch++) {
            const int jl = ch * 64;

            // ---- init s with shifted-BD (LDGs issue before MMAs) ----
            float s[2][8][4];
            #pragma unroll
            for (int mt = 0; mt < 2; mt++)
                #pragma unroll
                for (int nt = 0; nt < 8; nt++) {
                    int jc = j0 + jl + nt * 8 + 2 * qd;
                    float2 b0 = *(const float2*)(bdp + (size_t)irow[mt] * KLEN + jc);
                    float2 b1 = *(const float2*)(bdp + (size_t)(irow[mt] + 8) * KLEN + jc);
                    s[mt][nt][0] = b0.x; s[mt][nt][1] = b0.y;
                    s[mt][nt][2] = b1.x; s[mt][nt][3] = b1.y;
                }

            // ---- S += Q . K^T ----
            #pragma unroll
            for (int g = 0; g < 8; g++) {
                #pragma unroll
                for (int nt = 0; nt < 8; nt++) {
                    uint32_t bf[2];
                    int j = kb * 128 + jl + nt * 8 + row;
                    bf[0] = KsA[j][g * 8 + qd];
                    bf[1] = KsA[j][g * 8 + 4 + qd];
                    mma8(s[0][nt], qf[0][g], bf);
                    mma8(s[1][nt], qf[1][g], bf);
                }
            }

            // ---- scale ----
            #pragma unroll
            for (int mt = 0; mt < 2; mt++)
                #pragma unroll
                for (int nt = 0; nt < 8; nt++) {
                    s[mt][nt][0] *= 0.125f; s[mt][nt][1] *= 0.125f;
                    s[mt][nt][2] *= 0.125f; s[mt][nt][3] *= 0.125f;
                }

            // ---- online softmax ----
            #pragma unroll
            for (int mt = 0; mt < 2; mt++) {
                float tm0 = -3.402823466e38f, tm1 = -3.402823466e38f;
                #pragma unroll
                for (int nt = 0; nt < 8; nt++) {
                    tm0 = fmaxf(tm0, fmaxf(s[mt][nt][0], s[mt][nt][1]));
                    tm1 = fmaxf(tm1, fmaxf(s[mt][nt][2], s[mt][nt][3]));
                }
                tm0 = fmaxf(tm0, __shfl_xor_sync(0xffffffffu, tm0, 1));
                tm0 = fmaxf(tm0, __shfl_xor_sync(0xffffffffu, tm0, 2));
                tm1 = fmaxf(tm1, __shfl_xor_sync(0xffffffffu, tm1, 1));
                tm1 = fmaxf(tm1, __shfl_xor_sync(0xffffffffu, tm1, 2));

                float nm0 = fmaxf(mrow[mt][0], tm0), nm1 = fmaxf(mrow[mt][1], tm1);
                float sc0 = __expf(mrow[mt][0] - nm0), sc1 = __expf(mrow[mt][1] - nm1);
                mrow[mt][0] = nm0; mrow[mt][1] = nm1;

                float ps0 = 0.0f, ps1 = 0.0f;
                #pragma unroll
                for (int nt = 0; nt < 8; nt++) {
                    s[mt][nt][0] = __expf(s[mt][nt][0] - nm0);
                    s[mt][nt][1] = __expf(s[mt][nt][1] - nm0);
                    s[mt][nt][2] = __expf(s[mt][nt][2] - nm1);
                    s[mt][nt][3] = __expf(s[mt][nt][3] - nm1);
                    ps0 += s[mt][nt][0] + s[mt][nt][1];
                    ps1 += s[mt][nt][2] + s[mt][nt][3];
                }
                lrow[mt][0] = lrow[mt][0] * sc0 + ps0;
                lrow[mt][1] = lrow[mt][1] * sc1 + ps1;
                #pragma unroll
                for (int dt = 0; dt < 8; dt++) {
                    Ov[mt][dt][0] *= sc0; Ov[mt][dt][1] *= sc0;
                    Ov[mt][dt][2] *= sc1; Ov[mt][dt][3] *= sc1;
                }
            }

            // V[t] must be resident before first PV of this tile
            if (ch == 0) {
                cpa_wait<1>();
                __syncthreads();
            }

            // ---- P -> A-frags via shuffle, O += P.V ----
            #pragma unroll
            for (int g = 0; g < 8; g++) {
                uint32_t a[2][4];
                #pragma unroll
                for (int mt = 0; mt < 2; mt++) {
                    uint32_t p0 = f2tf(s[mt][g][0]), p1 = f2tf(s[mt][g][1]);
                    uint32_t p2 = f2tf(s[mt][g][2]), p3 = f2tf(s[mt][g][3]);
                    uint32_t t00 = __shfl_sync(0xffffffffu, p0, srcA);
                    uint32_t t01 = __shfl_sync(0xffffffffu, p1, srcA);
                    uint32_t t10 = __shfl_sync(0xffffffffu, p2, srcA);
                    uint32_t t11 = __shfl_sync(0xffffffffu, p3, srcA);
                    uint32_t u00 = __shfl_sync(0xffffffffu, p0, srcB);
                    uint32_t u01 = __shfl_sync(0xffffffffu, p1, srcB);
                    uint32_t u10 = __shfl_sync(0xffffffffu, p2, srcB);
                    uint32_t u11 = __shfl_sync(0xffffffffu, p3, srcB);
                    a[mt][0] = odd ? t01 : t00;
                    a[mt][1] = odd ? t11 : t10;
                    a[mt][2] = odd ? u01 : u00;
                    a[mt][3] = odd ? u11 : u10;
                }
                #pragma unroll
                for (int dt = 0; dt < 8; dt++) {
                    uint32_t bf[2];
                    bf[0] = Vs[jl + g * 8 + qd][dt * 8 + row];
                    bf[1] = Vs[jl + g * 8 + 4 + qd][dt * 8 + row];
                    mma8(Ov[0][dt], a[0], bf);
                    mma8(Ov[1][dt], a[1], bf);
                }
            }
        }

        // all warps done reading V[t]; stage V[t+1] (hidden under next S-phase)
        __syncthreads();
        if (t + 1 < 16) {
            #pragma unroll
            for (int it = 0; it < 16; it++) {
                int r = st_row + it * 8;
                const float* src = kv + ((size_t)(j0 + 128 + r) * 2 + b) * (2 * NHD) + NHD + n * DH + st_c4;
                cpa16(sbase + (uint32_t)(VBASE + r * 72 + st_c4) * 4, src);
            }
        }
        cpa_commit();
    }

    // drain any trailing empty groups
    cpa_wait<0>();

    #pragma unroll
    for (int mt = 0; mt < 2; mt++) {
        float l0 = lrow[mt][0], l1 = lrow[mt][1];
        l0 += __shfl_xor_sync(0xffffffffu, l0, 1);
        l0 += __shfl_xor_sync(0xffffffffu, l0, 2);
        l1 += __shfl_xor_sync(0xffffffffu, l1, 1);
        l1 += __shfl_xor_sync(0xffffffffu, l1, 2);
        float inv0 = 1.0f / l0, inv1 = 1.0f / l1;
        #pragma unroll
        for (int dt = 0; dt < 8; dt++) {
            int d = n * DH + dt * 8 + 2 * qd;
            *(float2*)&av[(size_t)(irow[mt] * 2 + b) * NHD + d] =
                make_float2(Ov[mt][dt][0] * inv0, Ov[mt][dt][1] * inv0);
            *(float2*)&av[(size_t)((irow[mt] + 8) * 2 + b) * NHD + d] =
                make_float2(Ov[mt][dt][2] * inv1, Ov[mt][dt][3] * inv1);
        }
    }
}

// ---------------------------------------------------------------------------
extern "C" void kernel_launch(void* const* d_in, const int* in_sizes, int n_in,
                              void* d_out, int out_size)
{
    const float* w   = (const float*)d_in[0];
    const float* r   = (const float*)d_in[1];
    const float* rwb = (const float*)d_in[2];
    const float* rrb = (const float*)d_in[3];
    const float* Wq  = (const float*)d_in[4];
    const float* Wkv = (const float*)d_in[5];
    const float* Wr  = (const float*)d_in[6];
    const float* Wo  = (const float*)d_in[7];
    float* out = (float*)d_out;

    float *qh, *kv, *rk, *bd, *av;
    cudaGetSymbolAddress((void**)&qh, g_qh);
    cudaGetSymbolAddress((void**)&kv, g_kv);
    cudaGetSymbolAddress((void**)&rk, g_rk);
    cudaGetSymbolAddress((void**)&bd, g_bd);
    cudaGetSymbolAddress((void**)&av, g_av);

    static cudaStream_t st1 = 0, st2 = 0;
    static cudaEvent_t ev0 = 0, evKV = 0, evR = 0;
    if (!st1) {
        cudaStreamCreateWithFlags(&st1, cudaStreamNonBlocking);
        cudaStreamCreateWithFlags(&st2, cudaStreamNonBlocking);
        cudaEventCreateWithFlags(&ev0,  cudaEventDisableTiming);
        cudaEventCreateWithFlags(&evKV, cudaEventDisableTiming);
        cudaEventCreateWithFlags(&evR,  cudaEventDisableTiming);
        cudaFuncSetAttribute(scores_bd_tf32,
                             cudaFuncAttributeMaxDynamicSharedMemorySize,
                             2 * 128 * 68 * 4);
        cudaFuncSetAttribute(attn_fused,
                             cudaFuncAttributeMaxDynamicSharedMemorySize,
                             (2 * KWORDS + 128 * 72) * 4);
    }
    const int score_smem = 2 * 128 * 68 * 4;
    const int fused_smem = (2 * KWORDS + 128 * 72) * 4;

    cudaEventRecord(ev0, 0);
    cudaStreamWaitEvent(st1, ev0, 0);
    cudaStreamWaitEvent(st2, ev0, 0);

    // stream 0: Wq projection
    gemm_tf32<<<dim3(1024 / 128, 2048 / 128), 256, 0, 0>>>(
        w + (size_t)QLEN * BSZ * DM, Wq, qh, 2048, 1024, 1024);

    // st1: Wkv projection (largest, overlapped)
    gemm_tf32<<<dim3(2048 / 128, 4096 / 128), 256, 0, st1>>>(
        w, Wkv, kv, 4096, 2048, 1024);
    cudaEventRecord(evKV, st1);

    // st2: zero diag + Wr projection
    zero_diag<<<32, 1024, 0, st2>>>(bd);
    gemm_tf32<<<dim3(1024 / 128, 2048 / 128), 256, 0, st2>>>(
        r, Wr, rk, 2048, 1024, 1024);
    cudaEventRecord(evR, st2);

    // stream 0: BD scores
    cudaStreamWaitEvent(0, evR, 0);
    scores_bd_tf32<<<dim3(RLEN / 128, QLEN / 128, 32), 256, score_smem, 0>>>(
        qh, rk, rrb, bd);

    // stream 0: fused attention
    cudaStreamWaitEvent(0, evKV, 0);
    attn_fused<<<dim3(QLEN / 128, BSZ * NH), 128, fused_smem, 0>>>(
        qh, kv, bd, rwb, av);

    // output projection
    gemm_tf32<<<dim3(1024 / 128, 2048 / 128), 256, 0, 0>>>(
        av, Wo, out, 2048, 1024, 1024);
}